// round 3
// baseline (speedup 1.0000x reference)
#include <cuda_runtime.h>

#define NN 50000
#define NE 800000

// Scratch (device globals; no allocation allowed)
__device__ float g_dis[NN];            // degree, then rsqrt(degree)
__device__ float g_t[NN * 128];        // linear-transform output (pre-aggregation)
__device__ float g_agg[NN * 128];      // aggregation accumulator
__device__ float g_h[NN * 128];        // post-activation features

static inline int cdiv(int a, int b) { return (a + b - 1) / b; }

// ---------------------------------------------------------------- degree/norm
__global__ void k_deg_init() {
    int i = blockIdx.x * blockDim.x + threadIdx.x;
    if (i < NN) g_dis[i] = 1.0f;  // self-loop contributes 1
}

__global__ void k_deg_count(const int* __restrict__ ei) {
    int e = blockIdx.x * blockDim.x + threadIdx.x;
    if (e < NE) atomicAdd(&g_dis[ei[NE + e]], 1.0f);
}

__global__ void k_dis_finalize() {
    int i = blockIdx.x * blockDim.x + threadIdx.x;
    if (i < NN) g_dis[i] = rsqrtf(g_dis[i]);  // deg >= 1 always
}

// ---------------------------------------------------------------- SGEMM
// g_t[M,N] = A[M,K] @ B[K,N];  g_agg[M,N] = dis[row]^2 * g_t (self-loop init)
// A = (useH ? g_h : Aparam).  BM=64, BN=64, BK=16, 256 threads, 4x4/thread.
__global__ __launch_bounds__(256) void sgemm_epi(
    const float* __restrict__ Aparam, const float* __restrict__ B,
    int M, int N, int K, int useH)
{
    const float* __restrict__ A = useH ? g_h : Aparam;

    __shared__ float As[64][20];   // padded rows (80B, 16B-aligned)
    __shared__ float Bs[16][64];

    const int tid = threadIdx.x;
    const int tr = tid >> 4;         // 0..15
    const int tc = tid & 15;         // 0..15
    const int m0 = blockIdx.y * 64;
    const int n0 = blockIdx.x * 64;

    const int rowA = tid >> 2;            // 0..63
    const int cA   = (tid & 3) * 4;       // 0,4,8,12
    const int rowB = tid >> 4;            // 0..15
    const int cB   = (tid & 15) * 4;      // 0..60

    float acc[4][4] = {};

    for (int k0 = 0; k0 < K; k0 += 16) {
        float4 av = make_float4(0.f, 0.f, 0.f, 0.f);
        if (m0 + rowA < M)
            av = *(const float4*)(A + (long long)(m0 + rowA) * K + k0 + cA);
        *(float4*)&As[rowA][cA] = av;

        float4 bv = *(const float4*)(B + (long long)(k0 + rowB) * N + n0 + cB);
        *(float4*)&Bs[rowB][cB] = bv;
        __syncthreads();

#pragma unroll
        for (int k = 0; k < 16; k++) {
            float am[4];
#pragma unroll
            for (int i = 0; i < 4; i++) am[i] = As[tr * 4 + i][k];
            float4 b4 = *(float4*)&Bs[k][tc * 4];
            float bn[4] = {b4.x, b4.y, b4.z, b4.w};
#pragma unroll
            for (int i = 0; i < 4; i++)
#pragma unroll
                for (int j = 0; j < 4; j++) acc[i][j] += am[i] * bn[j];
        }
        __syncthreads();
    }

#pragma unroll
    for (int i = 0; i < 4; i++) {
        int r = m0 + tr * 4 + i;
        if (r < M) {
            float ds = g_dis[r];
            float d2 = ds * ds;
            long long base = (long long)r * N + n0 + tc * 4;
#pragma unroll
            for (int j = 0; j < 4; j++) {
                g_t[base + j]   = acc[i][j];
                g_agg[base + j] = d2 * acc[i][j];
            }
        }
    }
}

// ---------------------------------------------------------------- edge aggregation
// g_agg[dst] += dis[src]*dis[dst] * g_t[src]; F/4 lanes per edge, float4 gather.
template <int F>
__global__ void k_edge(const int* __restrict__ ei)
{
    const int L = F / 4;
    long long idx = (long long)blockIdx.x * blockDim.x + threadIdx.x;
    long long e = idx / L;
    int l = (int)(idx & (L - 1));
    if (e >= NE) return;
    int s = ei[e];
    int d = ei[NE + e];
    float w = g_dis[s] * g_dis[d];
    float4 v = *(const float4*)(g_t + (long long)s * F + l * 4);
    float* o = g_agg + (long long)d * F + l * 4;
    atomicAdd(o + 0, v.x * w);
    atomicAdd(o + 1, v.y * w);
    atomicAdd(o + 2, v.z * w);
    atomicAdd(o + 3, v.w * w);
}

// ---------------------------------------------------------------- bias + relu
__global__ void k_bias_relu(const float* __restrict__ b, int total, int mask)
{
    int i = blockIdx.x * blockDim.x + threadIdx.x;
    if (i < total) {
        float v = g_agg[i] + b[i & mask];
        g_h[i] = fmaxf(v, 0.f);
    }
}

// ---------------------------------------------------------------- final layer
// h3 = g_agg(64) + b2 (no relu); write h3 to out[N..]; out[i] = h3 . Wout + bout
__global__ void k_final(const float* __restrict__ b2,
                        const float* __restrict__ Wout,
                        const float* __restrict__ bout,
                        float* __restrict__ out)
{
    int gtid = blockIdx.x * blockDim.x + threadIdx.x;
    int node = gtid >> 5;
    int lane = gtid & 31;
    if (node >= NN) return;
    const float* a = g_agg + (long long)node * 64;
    int f = lane * 2;
    float v0 = a[f]     + b2[f];
    float v1 = a[f + 1] + b2[f + 1];
    float* hout = out + NN + (long long)node * 64;
    hout[f]     = v0;
    hout[f + 1] = v1;
    float p = v0 * Wout[f] + v1 * Wout[f + 1];
#pragma unroll
    for (int o = 16; o; o >>= 1) p += __shfl_down_sync(0xFFFFFFFFu, p, o);
    if (lane == 0) out[node] = p + bout[0];
}

// ---------------------------------------------------------------- launcher
extern "C" void kernel_launch(void* const* d_in, const int* in_sizes, int n_in,
                              void* d_out, int out_size)
{
    const float* x    = (const float*)d_in[0];
    const int*   ei   = (const int*)d_in[1];     // int32 (JAX x64 disabled)
    const float* W1   = (const float*)d_in[2];
    const float* b1   = (const float*)d_in[3];
    const float* Wh   = (const float*)d_in[4];
    const float* bh   = (const float*)d_in[5];
    const float* W2   = (const float*)d_in[6];
    const float* b2   = (const float*)d_in[7];
    const float* Wout = (const float*)d_in[8];
    const float* bout = (const float*)d_in[9];
    float*       out  = (float*)d_out;

    // normalization
    k_deg_init<<<cdiv(NN, 256), 256>>>();
    k_deg_count<<<cdiv(NE, 256), 256>>>(ei);
    k_dis_finalize<<<cdiv(NN, 256), 256>>>();

    dim3 g128(2, cdiv(NN, 64));   // N=128
    dim3 g64(1, cdiv(NN, 64));    // N=64

    // layer 1: x@W1 -> t, agg=dis^2*t ; edges ; relu(agg+b1) -> h
    sgemm_epi<<<g128, 256>>>(x, W1, NN, 128, 128, 0);
    k_edge<128><<<cdiv(NE * 32, 256), 256>>>(ei);
    k_bias_relu<<<cdiv(NN * 128, 256), 256>>>(b1, NN * 128, 127);

    // layer 2
    sgemm_epi<<<g128, 256>>>(nullptr, Wh, NN, 128, 128, 1);
    k_edge<128><<<cdiv(NE * 32, 256), 256>>>(ei);
    k_bias_relu<<<cdiv(NN * 128, 256), 256>>>(bh, NN * 128, 127);

    // layer 3 (128 -> 64, no relu, bias folded into final kernel)
    sgemm_epi<<<g64, 256>>>(nullptr, W2, NN, 64, 128, 1);
    k_edge<64><<<cdiv(NE * 16, 256), 256>>>(ei);

    // h out + readout
    k_final<<<cdiv(NN * 32, 256), 256>>>(b2, Wout, bout, out);
}

// round 4
// speedup vs baseline: 2.5214x; 2.5214x over previous
#include <cuda_runtime.h>

#define NN 50000
#define NE 800000
#define NB 196              // cdiv(NN,256)

// Scratch (device globals; no allocation allowed)
__device__ float g_dis[NN];
__device__ int   g_deg[NN];
__device__ int   g_scan[NN];
__device__ int   g_bsum[256];
__device__ int   g_boff[256];
__device__ int   g_rowptr[NN + 1];
__device__ int   g_cur[NN];
__device__ int   g_cs[NE];           // CSR src ids (grouped by dst)
__device__ float g_cw[NE];           // CSR edge weights dis[s]*dis[d]
__device__ float g_t[NN * 128];      // linear-transform output
__device__ float g_h[NN * 128];      // post-activation features

static inline int cdiv(int a, int b) { return (a + b - 1) / b; }

// ---------------------------------------------------------------- degree
__global__ void k_deg_init() {
    int i = blockIdx.x * blockDim.x + threadIdx.x;
    if (i < NN) g_deg[i] = 0;
}

__global__ void k_deg_count(const int* __restrict__ ei) {
    int e = blockIdx.x * blockDim.x + threadIdx.x;
    if (e < NE) atomicAdd(&g_deg[ei[NE + e]], 1);
}

__global__ void k_dis_finalize() {
    int i = blockIdx.x * blockDim.x + threadIdx.x;
    if (i < NN) g_dis[i] = rsqrtf(1.0f + (float)g_deg[i]);  // +1 self-loop
}

// ---------------------------------------------------------------- scan (3-kernel)
__global__ void k_scan1() {
    __shared__ int s[256];
    int i = blockIdx.x * 256 + threadIdx.x;
    int v = (i < NN) ? g_deg[i] : 0;
    s[threadIdx.x] = v;
    __syncthreads();
#pragma unroll
    for (int off = 1; off < 256; off <<= 1) {
        int t = (threadIdx.x >= off) ? s[threadIdx.x - off] : 0;
        __syncthreads();
        s[threadIdx.x] += t;
        __syncthreads();
    }
    if (i < NN) g_scan[i] = s[threadIdx.x];          // inclusive
    if (threadIdx.x == 255) g_bsum[blockIdx.x] = s[255];
}

__global__ void k_scan2() {
    __shared__ int s[256];
    int v = (threadIdx.x < NB) ? g_bsum[threadIdx.x] : 0;
    s[threadIdx.x] = v;
    __syncthreads();
#pragma unroll
    for (int off = 1; off < 256; off <<= 1) {
        int t = (threadIdx.x >= off) ? s[threadIdx.x - off] : 0;
        __syncthreads();
        s[threadIdx.x] += t;
        __syncthreads();
    }
    if (threadIdx.x < NB) g_boff[threadIdx.x] = s[threadIdx.x] - v;  // exclusive
}

__global__ void k_scan3() {
    int i = blockIdx.x * 256 + threadIdx.x;
    if (i < NN) {
        int rp = g_scan[i] - g_deg[i] + g_boff[blockIdx.x];
        g_rowptr[i] = rp;
        g_cur[i] = rp;
    }
    if (i == 0) g_rowptr[NN] = NE;
}

// ---------------------------------------------------------------- CSR scatter
__global__ void k_scatter(const int* __restrict__ ei) {
    int e = blockIdx.x * blockDim.x + threadIdx.x;
    if (e >= NE) return;
    int s = ei[e];
    int d = ei[NE + e];
    int pos = atomicAdd(&g_cur[d], 1);
    g_cs[pos] = s;
    g_cw[pos] = g_dis[s] * g_dis[d];
}

// ---------------------------------------------------------------- SGEMM -> g_t
// BM=64, BN=64, BK=16, 256 threads, 4x4/thread. A-tile stored transposed.
__global__ __launch_bounds__(256) void sgemm_t(
    const float* __restrict__ Aparam, const float* __restrict__ B,
    int M, int N, int K, int useH)
{
    const float* __restrict__ A = useH ? g_h : Aparam;

    __shared__ float Ast[16][68];   // [k][row], pad 68 -> <=2-way store conflict
    __shared__ float Bs[16][64];

    const int tid = threadIdx.x;
    const int tr = tid >> 4;         // 0..15
    const int tc = tid & 15;         // 0..15
    const int m0 = blockIdx.y * 64;
    const int n0 = blockIdx.x * 64;

    const int rowA = tid >> 2;            // 0..63
    const int cA   = (tid & 3) * 4;       // 0,4,8,12
    const int rowB = tid >> 4;            // 0..15
    const int cB   = (tid & 15) * 4;      // 0..60

    float acc[4][4] = {};

    for (int k0 = 0; k0 < K; k0 += 16) {
        float4 av = make_float4(0.f, 0.f, 0.f, 0.f);
        if (m0 + rowA < M)
            av = *(const float4*)(A + (long long)(m0 + rowA) * K + k0 + cA);
        Ast[cA + 0][rowA] = av.x;
        Ast[cA + 1][rowA] = av.y;
        Ast[cA + 2][rowA] = av.z;
        Ast[cA + 3][rowA] = av.w;

        float4 bv = *(const float4*)(B + (long long)(k0 + rowB) * N + n0 + cB);
        *(float4*)&Bs[rowB][cB] = bv;
        __syncthreads();

#pragma unroll
        for (int k = 0; k < 16; k++) {
            float4 a4 = *(float4*)&Ast[k][tr * 4];
            float4 b4 = *(float4*)&Bs[k][tc * 4];
            float am[4] = {a4.x, a4.y, a4.z, a4.w};
            float bn[4] = {b4.x, b4.y, b4.z, b4.w};
#pragma unroll
            for (int i = 0; i < 4; i++)
#pragma unroll
                for (int j = 0; j < 4; j++) acc[i][j] += am[i] * bn[j];
        }
        __syncthreads();
    }

#pragma unroll
    for (int i = 0; i < 4; i++) {
        int r = m0 + tr * 4 + i;
        if (r < M) {
            long long base = (long long)r * N + n0 + tc * 4;
            float4 v = make_float4(acc[i][0], acc[i][1], acc[i][2], acc[i][3]);
            *(float4*)&g_t[base] = v;
        }
    }
}

// ---------------------------------------------------------------- CSR aggregation
// g_h[node] = relu( dis^2*t[node] + sum_e w_e * t[src_e] + bias ), F=128.
__global__ __launch_bounds__(128) void k_agg128(const float* __restrict__ bias)
{
    __shared__ int   s_src[128];
    __shared__ float s_w[128];
    const int node = blockIdx.x;
    const int tid  = threadIdx.x;
    const int beg = g_rowptr[node];
    const int end = g_rowptr[node + 1];
    const float ds = g_dis[node];

    float acc = ds * ds * g_t[(long long)node * 128 + tid];

    for (int base = beg; base < end; base += 128) {
        int n = min(128, end - base);
        if (tid < n) { s_src[tid] = g_cs[base + tid]; s_w[tid] = g_cw[base + tid]; }
        __syncthreads();
        int j = 0;
        for (; j + 4 <= n; j += 4) {
            float v0 = g_t[(long long)s_src[j + 0] * 128 + tid];
            float v1 = g_t[(long long)s_src[j + 1] * 128 + tid];
            float v2 = g_t[(long long)s_src[j + 2] * 128 + tid];
            float v3 = g_t[(long long)s_src[j + 3] * 128 + tid];
            acc += s_w[j + 0] * v0;
            acc += s_w[j + 1] * v1;
            acc += s_w[j + 2] * v2;
            acc += s_w[j + 3] * v3;
        }
        for (; j < n; j++)
            acc += s_w[j] * g_t[(long long)s_src[j] * 128 + tid];
        __syncthreads();
    }

    g_h[(long long)node * 128 + tid] = fmaxf(acc + bias[tid], 0.f);
}

// ---------------------------------------------------------------- fused layer-3 agg + readout
// v = dis^2*t64[node] + sum w*t64[src] + b2; out[NN+node*64+f]=v; out[node]=v.Wout+bout
__global__ __launch_bounds__(64) void k_final64(
    const float* __restrict__ b2,
    const float* __restrict__ Wout,
    const float* __restrict__ bout,
    float* __restrict__ out)
{
    __shared__ int   s_src[64];
    __shared__ float s_w[64];
    __shared__ float s_part[2];
    const int node = blockIdx.x;
    const int tid  = threadIdx.x;
    const int beg = g_rowptr[node];
    const int end = g_rowptr[node + 1];
    const float ds = g_dis[node];

    float acc = ds * ds * g_t[(long long)node * 64 + tid];

    for (int base = beg; base < end; base += 64) {
        int n = min(64, end - base);
        if (tid < n) { s_src[tid] = g_cs[base + tid]; s_w[tid] = g_cw[base + tid]; }
        __syncthreads();
        int j = 0;
        for (; j + 4 <= n; j += 4) {
            float v0 = g_t[(long long)s_src[j + 0] * 64 + tid];
            float v1 = g_t[(long long)s_src[j + 1] * 64 + tid];
            float v2 = g_t[(long long)s_src[j + 2] * 64 + tid];
            float v3 = g_t[(long long)s_src[j + 3] * 64 + tid];
            acc += s_w[j + 0] * v0;
            acc += s_w[j + 1] * v1;
            acc += s_w[j + 2] * v2;
            acc += s_w[j + 3] * v3;
        }
        for (; j < n; j++)
            acc += s_w[j] * g_t[(long long)s_src[j] * 64 + tid];
        __syncthreads();
    }

    float v = acc + b2[tid];
    out[NN + (long long)node * 64 + tid] = v;

    float p = v * Wout[tid];
#pragma unroll
    for (int o = 16; o; o >>= 1) p += __shfl_down_sync(0xFFFFFFFFu, p, o);
    if ((tid & 31) == 0) s_part[tid >> 5] = p;
    __syncthreads();
    if (tid == 0) out[node] = s_part[0] + s_part[1] + bout[0];
}

// ---------------------------------------------------------------- launcher
extern "C" void kernel_launch(void* const* d_in, const int* in_sizes, int n_in,
                              void* d_out, int out_size)
{
    const float* x    = (const float*)d_in[0];
    const int*   ei   = (const int*)d_in[1];     // int32 (JAX x64 disabled)
    const float* W1   = (const float*)d_in[2];
    const float* b1   = (const float*)d_in[3];
    const float* Wh   = (const float*)d_in[4];
    const float* bh   = (const float*)d_in[5];
    const float* W2   = (const float*)d_in[6];
    const float* b2   = (const float*)d_in[7];
    const float* Wout = (const float*)d_in[8];
    const float* bout = (const float*)d_in[9];
    float*       out  = (float*)d_out;

    // normalization + CSR build (once, reused by all 3 layers)
    k_deg_init<<<cdiv(NN, 256), 256>>>();
    k_deg_count<<<cdiv(NE, 256), 256>>>(ei);
    k_dis_finalize<<<cdiv(NN, 256), 256>>>();
    k_scan1<<<NB, 256>>>();
    k_scan2<<<1, 256>>>();
    k_scan3<<<NB, 256>>>();
    k_scatter<<<cdiv(NE, 256), 256>>>(ei);

    dim3 g128(2, cdiv(NN, 64));   // N=128
    dim3 g64(1, cdiv(NN, 64));    // N=64

    // layer 1
    sgemm_t<<<g128, 256>>>(x, W1, NN, 128, 128, 0);
    k_agg128<<<NN, 128>>>(b1);
    // layer 2
    sgemm_t<<<g128, 256>>>(nullptr, Wh, NN, 128, 128, 1);
    k_agg128<<<NN, 128>>>(bh);
    // layer 3 (128 -> 64) + fused readout
    sgemm_t<<<g64, 256>>>(nullptr, W2, NN, 64, 128, 1);
    k_final64<<<NN, 64>>>(b2, Wout, bout, out);
}

// round 5
// speedup vs baseline: 2.6395x; 1.0469x over previous
#include <cuda_runtime.h>

#define NN 50000
#define NE 800000
#define NB 196              // cdiv(NN,256)

// Scratch (device globals; no allocation allowed)
__device__ float g_dis[NN];
__device__ int   g_deg[NN];
__device__ int   g_scan[NN];
__device__ int   g_bsum[256];
__device__ int   g_boff[256];
__device__ int   g_rowptr[NN + 1];
__device__ int   g_cur[NN];
__device__ int   g_cs[NE];           // CSR src ids (grouped by dst)
__device__ float g_cw[NE];           // CSR edge weights dis[s]*dis[d]
__device__ float g_t[NN * 128];      // linear-transform output
__device__ float g_h[NN * 128];      // post-activation features

static inline int cdiv(int a, int b) { return (a + b - 1) / b; }

// ---------------------------------------------------------------- degree
__global__ void k_deg_init() {
    int i = blockIdx.x * blockDim.x + threadIdx.x;
    if (i < NN) g_deg[i] = 0;
}

__global__ void k_deg_count(const int* __restrict__ ei) {
    int e = blockIdx.x * blockDim.x + threadIdx.x;
    if (e < NE) atomicAdd(&g_deg[ei[NE + e]], 1);
}

__global__ void k_dis_finalize() {
    int i = blockIdx.x * blockDim.x + threadIdx.x;
    if (i < NN) g_dis[i] = rsqrtf(1.0f + (float)g_deg[i]);  // +1 self-loop
}

// ---------------------------------------------------------------- scan (3-kernel)
__global__ void k_scan1() {
    __shared__ int s[256];
    int i = blockIdx.x * 256 + threadIdx.x;
    int v = (i < NN) ? g_deg[i] : 0;
    s[threadIdx.x] = v;
    __syncthreads();
#pragma unroll
    for (int off = 1; off < 256; off <<= 1) {
        int t = (threadIdx.x >= off) ? s[threadIdx.x - off] : 0;
        __syncthreads();
        s[threadIdx.x] += t;
        __syncthreads();
    }
    if (i < NN) g_scan[i] = s[threadIdx.x];          // inclusive
    if (threadIdx.x == 255) g_bsum[blockIdx.x] = s[255];
}

__global__ void k_scan2() {
    __shared__ int s[256];
    int v = (threadIdx.x < NB) ? g_bsum[threadIdx.x] : 0;
    s[threadIdx.x] = v;
    __syncthreads();
#pragma unroll
    for (int off = 1; off < 256; off <<= 1) {
        int t = (threadIdx.x >= off) ? s[threadIdx.x - off] : 0;
        __syncthreads();
        s[threadIdx.x] += t;
        __syncthreads();
    }
    if (threadIdx.x < NB) g_boff[threadIdx.x] = s[threadIdx.x] - v;  // exclusive
}

__global__ void k_scan3() {
    int i = blockIdx.x * 256 + threadIdx.x;
    if (i < NN) {
        int rp = g_scan[i] - g_deg[i] + g_boff[blockIdx.x];
        g_rowptr[i] = rp;
        g_cur[i] = rp;
    }
    if (i == 0) g_rowptr[NN] = NE;
}

// ---------------------------------------------------------------- CSR scatter
__global__ void k_scatter(const int* __restrict__ ei) {
    int e = blockIdx.x * blockDim.x + threadIdx.x;
    if (e >= NE) return;
    int s = ei[e];
    int d = ei[NE + e];
    int pos = atomicAdd(&g_cur[d], 1);
    g_cs[pos] = s;
    g_cw[pos] = g_dis[s] * g_dis[d];
}

// ---------------------------------------------------------------- tf32 helpers
__device__ __forceinline__ unsigned tf32_of(float x) {
    unsigned r;
    asm("cvt.rna.tf32.f32 %0, %1;" : "=r"(r) : "f"(x));
    return r;
}

__device__ __forceinline__ void tf32_split(float x, unsigned& hi, unsigned& lo) {
    hi = tf32_of(x);
    lo = tf32_of(x - __uint_as_float(hi));
}

__device__ __forceinline__ void mma_tf32(float* d, const unsigned* a, const unsigned* b) {
    asm("mma.sync.aligned.m16n8k8.row.col.f32.tf32.tf32.f32 "
        "{%0,%1,%2,%3}, {%4,%5,%6,%7}, {%8,%9}, {%0,%1,%2,%3};"
        : "+f"(d[0]), "+f"(d[1]), "+f"(d[2]), "+f"(d[3])
        : "r"(a[0]), "r"(a[1]), "r"(a[2]), "r"(a[3]), "r"(b[0]), "r"(b[1]));
}

// ---------------------------------------------------------------- 3xTF32 GEMM (N=128, K=128)
// g_t[M,128] = A[M,128] @ B[128,128].  BM=128, BN=128, BK=16.
// 8 warps, warp tile 32x64, mma m16n8k8, hi/lo split for fp32-grade accuracy.
#define AST 20    // As row stride (floats): conflict-free frag loads
#define BST 136   // Bs row stride

__global__ __launch_bounds__(256, 1) void gemm_tf32(
    const float* __restrict__ Aparam, const float* __restrict__ B,
    int M, int useH)
{
    const float* __restrict__ A = useH ? g_h : Aparam;

    __shared__ float As[128 * AST];   // [m][k] m-major, stride 20
    __shared__ float Bs[16 * BST];    // [k][n], stride 136

    const int tid = threadIdx.x;
    const int w = tid >> 5;
    const int lane = tid & 31;
    const int g = lane >> 2;        // group 0..7
    const int tig = lane & 3;       // 0..3
    const int warp_m = (w & 3) * 32;
    const int warp_n = (w >> 2) * 64;
    const int m0 = blockIdx.y * 128;

    float acc[2][8][4];
#pragma unroll
    for (int i = 0; i < 2; i++)
#pragma unroll
        for (int j = 0; j < 8; j++)
#pragma unroll
            for (int c = 0; c < 4; c++) acc[i][j][c] = 0.f;

    for (int k0 = 0; k0 < 128; k0 += 16) {
        // load A tile 128x16 (transposed-access layout [m][k])
#pragma unroll
        for (int i = 0; i < 2; i++) {
            int idx = tid * 2 + i;            // 0..511
            int row = idx >> 2;               // 0..127
            int kc = (idx & 3) * 4;           // 0,4,8,12
            float4 av = make_float4(0.f, 0.f, 0.f, 0.f);
            if (m0 + row < M)
                av = *(const float4*)(A + (long long)(m0 + row) * 128 + k0 + kc);
            As[row * AST + kc + 0] = av.x;
            As[row * AST + kc + 1] = av.y;
            As[row * AST + kc + 2] = av.z;
            As[row * AST + kc + 3] = av.w;
        }
        // load B tile 16x128
#pragma unroll
        for (int i = 0; i < 2; i++) {
            int idx = tid * 2 + i;            // 0..511
            int row = idx >> 5;               // 0..15
            int c4 = (idx & 31) * 4;          // 0..124
            float4 bv = *(const float4*)(B + (long long)(k0 + row) * 128 + c4);
            *(float4*)&Bs[row * BST + c4] = bv;
        }
        __syncthreads();

#pragma unroll
        for (int ks = 0; ks < 16; ks += 8) {
            // A fragments: 2 m-tiles
            unsigned ahi[2][4], alo[2][4];
#pragma unroll
            for (int mt = 0; mt < 2; mt++) {
                int base = warp_m + mt * 16;
                float a0 = As[(base + g) * AST + ks + tig];
                float a1 = As[(base + g + 8) * AST + ks + tig];
                float a2 = As[(base + g) * AST + ks + tig + 4];
                float a3 = As[(base + g + 8) * AST + ks + tig + 4];
                tf32_split(a0, ahi[mt][0], alo[mt][0]);
                tf32_split(a1, ahi[mt][1], alo[mt][1]);
                tf32_split(a2, ahi[mt][2], alo[mt][2]);
                tf32_split(a3, ahi[mt][3], alo[mt][3]);
            }
            // B fragments: 8 n-tiles
            unsigned bhi[8][2], blo[8][2];
#pragma unroll
            for (int nt = 0; nt < 8; nt++) {
                int col = warp_n + nt * 8 + g;
                float b0 = Bs[(ks + tig) * BST + col];
                float b1 = Bs[(ks + tig + 4) * BST + col];
                tf32_split(b0, bhi[nt][0], blo[nt][0]);
                tf32_split(b1, bhi[nt][1], blo[nt][1]);
            }
#pragma unroll
            for (int mt = 0; mt < 2; mt++)
#pragma unroll
                for (int nt = 0; nt < 8; nt++) {
                    mma_tf32(acc[mt][nt], alo[mt], bhi[nt]);
                    mma_tf32(acc[mt][nt], ahi[mt], blo[nt]);
                    mma_tf32(acc[mt][nt], ahi[mt], bhi[nt]);
                }
        }
        __syncthreads();
    }

    // epilogue: acc[mt][nt][c]: row = m0+warp_m+mt*16+g(+8), col = warp_n+nt*8+tig*2(+1)
#pragma unroll
    for (int mt = 0; mt < 2; mt++) {
#pragma unroll
        for (int half = 0; half < 2; half++) {
            int r = m0 + warp_m + mt * 16 + g + half * 8;
            if (r < M) {
#pragma unroll
                for (int nt = 0; nt < 8; nt++) {
                    int c = warp_n + nt * 8 + tig * 2;
                    float2 v = half ? make_float2(acc[mt][nt][2], acc[mt][nt][3])
                                    : make_float2(acc[mt][nt][0], acc[mt][nt][1]);
                    *(float2*)&g_t[(long long)r * 128 + c] = v;
                }
            }
        }
    }
}

// ---------------------------------------------------------------- SGEMM (layer 3, N=64)
__global__ __launch_bounds__(256) void sgemm_t(
    const float* __restrict__ B, int M, int N, int K)
{
    const float* __restrict__ A = g_h;

    __shared__ float Ast[16][68];
    __shared__ float Bs[16][64];

    const int tid = threadIdx.x;
    const int tr = tid >> 4;
    const int tc = tid & 15;
    const int m0 = blockIdx.y * 64;
    const int n0 = blockIdx.x * 64;

    const int rowA = tid >> 2;
    const int cA   = (tid & 3) * 4;
    const int rowB = tid >> 4;
    const int cB   = (tid & 15) * 4;

    float acc[4][4] = {};

    for (int k0 = 0; k0 < K; k0 += 16) {
        float4 av = make_float4(0.f, 0.f, 0.f, 0.f);
        if (m0 + rowA < M)
            av = *(const float4*)(A + (long long)(m0 + rowA) * K + k0 + cA);
        Ast[cA + 0][rowA] = av.x;
        Ast[cA + 1][rowA] = av.y;
        Ast[cA + 2][rowA] = av.z;
        Ast[cA + 3][rowA] = av.w;

        float4 bv = *(const float4*)(B + (long long)(k0 + rowB) * N + n0 + cB);
        *(float4*)&Bs[rowB][cB] = bv;
        __syncthreads();

#pragma unroll
        for (int k = 0; k < 16; k++) {
            float4 a4 = *(float4*)&Ast[k][tr * 4];
            float4 b4 = *(float4*)&Bs[k][tc * 4];
            float am[4] = {a4.x, a4.y, a4.z, a4.w};
            float bn[4] = {b4.x, b4.y, b4.z, b4.w};
#pragma unroll
            for (int i = 0; i < 4; i++)
#pragma unroll
                for (int j = 0; j < 4; j++) acc[i][j] += am[i] * bn[j];
        }
        __syncthreads();
    }

#pragma unroll
    for (int i = 0; i < 4; i++) {
        int r = m0 + tr * 4 + i;
        if (r < M) {
            long long base = (long long)r * N + n0 + tc * 4;
            float4 v = make_float4(acc[i][0], acc[i][1], acc[i][2], acc[i][3]);
            *(float4*)&g_t[base] = v;
        }
    }
}

// ---------------------------------------------------------------- CSR aggregation
__global__ __launch_bounds__(128) void k_agg128(const float* __restrict__ bias)
{
    __shared__ int   s_src[128];
    __shared__ float s_w[128];
    const int node = blockIdx.x;
    const int tid  = threadIdx.x;
    const int beg = g_rowptr[node];
    const int end = g_rowptr[node + 1];
    const float ds = g_dis[node];

    float acc = ds * ds * g_t[(long long)node * 128 + tid];

    for (int base = beg; base < end; base += 128) {
        int n = min(128, end - base);
        if (tid < n) { s_src[tid] = g_cs[base + tid]; s_w[tid] = g_cw[base + tid]; }
        __syncthreads();
        int j = 0;
        for (; j + 4 <= n; j += 4) {
            float v0 = g_t[(long long)s_src[j + 0] * 128 + tid];
            float v1 = g_t[(long long)s_src[j + 1] * 128 + tid];
            float v2 = g_t[(long long)s_src[j + 2] * 128 + tid];
            float v3 = g_t[(long long)s_src[j + 3] * 128 + tid];
            acc += s_w[j + 0] * v0;
            acc += s_w[j + 1] * v1;
            acc += s_w[j + 2] * v2;
            acc += s_w[j + 3] * v3;
        }
        for (; j < n; j++)
            acc += s_w[j] * g_t[(long long)s_src[j] * 128 + tid];
        __syncthreads();
    }

    g_h[(long long)node * 128 + tid] = fmaxf(acc + bias[tid], 0.f);
}

// ---------------------------------------------------------------- fused layer-3 agg + readout
__global__ __launch_bounds__(64) void k_final64(
    const float* __restrict__ b2,
    const float* __restrict__ Wout,
    const float* __restrict__ bout,
    float* __restrict__ out)
{
    __shared__ int   s_src[64];
    __shared__ float s_w[64];
    __shared__ float s_part[2];
    const int node = blockIdx.x;
    const int tid  = threadIdx.x;
    const int beg = g_rowptr[node];
    const int end = g_rowptr[node + 1];
    const float ds = g_dis[node];

    float acc = ds * ds * g_t[(long long)node * 64 + tid];

    for (int base = beg; base < end; base += 64) {
        int n = min(64, end - base);
        if (tid < n) { s_src[tid] = g_cs[base + tid]; s_w[tid] = g_cw[base + tid]; }
        __syncthreads();
        int j = 0;
        for (; j + 4 <= n; j += 4) {
            float v0 = g_t[(long long)s_src[j + 0] * 64 + tid];
            float v1 = g_t[(long long)s_src[j + 1] * 64 + tid];
            float v2 = g_t[(long long)s_src[j + 2] * 64 + tid];
            float v3 = g_t[(long long)s_src[j + 3] * 64 + tid];
            acc += s_w[j + 0] * v0;
            acc += s_w[j + 1] * v1;
            acc += s_w[j + 2] * v2;
            acc += s_w[j + 3] * v3;
        }
        for (; j < n; j++)
            acc += s_w[j] * g_t[(long long)s_src[j] * 64 + tid];
        __syncthreads();
    }

    float v = acc + b2[tid];
    out[NN + (long long)node * 64 + tid] = v;

    float p = v * Wout[tid];
#pragma unroll
    for (int o = 16; o; o >>= 1) p += __shfl_down_sync(0xFFFFFFFFu, p, o);
    if ((tid & 31) == 0) s_part[tid >> 5] = p;
    __syncthreads();
    if (tid == 0) out[node] = s_part[0] + s_part[1] + bout[0];
}

// ---------------------------------------------------------------- launcher
extern "C" void kernel_launch(void* const* d_in, const int* in_sizes, int n_in,
                              void* d_out, int out_size)
{
    const float* x    = (const float*)d_in[0];
    const int*   ei   = (const int*)d_in[1];     // int32 (JAX x64 disabled)
    const float* W1   = (const float*)d_in[2];
    const float* b1   = (const float*)d_in[3];
    const float* Wh   = (const float*)d_in[4];
    const float* bh   = (const float*)d_in[5];
    const float* W2   = (const float*)d_in[6];
    const float* b2   = (const float*)d_in[7];
    const float* Wout = (const float*)d_in[8];
    const float* bout = (const float*)d_in[9];
    float*       out  = (float*)d_out;

    // normalization + CSR build (once, reused by all 3 layers)
    k_deg_init<<<cdiv(NN, 256), 256>>>();
    k_deg_count<<<cdiv(NE, 256), 256>>>(ei);
    k_dis_finalize<<<cdiv(NN, 256), 256>>>();
    k_scan1<<<NB, 256>>>();
    k_scan2<<<1, 256>>>();
    k_scan3<<<NB, 256>>>();
    k_scatter<<<cdiv(NE, 256), 256>>>(ei);

    dim3 gt(1, cdiv(NN, 128));    // tf32 GEMM grid (BM=128)
    dim3 g64(1, cdiv(NN, 64));

    // layer 1
    gemm_tf32<<<gt, 256>>>(x, W1, NN, 0);
    k_agg128<<<NN, 128>>>(b1);
    // layer 2
    gemm_tf32<<<gt, 256>>>(nullptr, Wh, NN, 1);
    k_agg128<<<NN, 128>>>(bh);
    // layer 3 (128 -> 64) + fused readout
    sgemm_t<<<g64, 256>>>(W2, NN, 64, 128);
    k_final64<<<NN, 64>>>(b2, Wout, bout, out);
}

// round 6
// speedup vs baseline: 2.7372x; 1.0370x over previous
#include <cuda_runtime.h>

#define NN 50000
#define NE 800000
#define NB 196              // cdiv(NN,256)

// Scratch (device globals; no allocation allowed)
__device__ float g_dis[NN];
__device__ int   g_deg[NN];
__device__ int   g_scan[NN];
__device__ int   g_bsum[256];
__device__ int   g_boff[256];
__device__ int   g_rowptr[NN + 1];
__device__ int   g_cur[NN];
__device__ int   g_cs[NE];           // CSR src ids (grouped by dst)
__device__ float g_cw[NE];           // CSR edge weights dis[s]*dis[d]
__device__ float g_t[NN * 128];      // linear-transform output
__device__ float g_h[NN * 128];      // post-activation features

static inline int cdiv(int a, int b) { return (a + b - 1) / b; }

// ---------------------------------------------------------------- degree
__global__ void k_deg_init() {
    int i = blockIdx.x * blockDim.x + threadIdx.x;
    if (i < NN) g_deg[i] = 0;
}

__global__ void k_deg_count(const int* __restrict__ ei) {
    int e = blockIdx.x * blockDim.x + threadIdx.x;
    if (e < NE) atomicAdd(&g_deg[ei[NE + e]], 1);
}

// ---------------------------------------------------------------- scan (3-kernel)
// scan1 also finalizes g_dis = rsqrt(1+deg)
__global__ void k_scan1() {
    __shared__ int s[256];
    int i = blockIdx.x * 256 + threadIdx.x;
    int v = (i < NN) ? g_deg[i] : 0;
    if (i < NN) g_dis[i] = rsqrtf(1.0f + (float)v);
    s[threadIdx.x] = v;
    __syncthreads();
#pragma unroll
    for (int off = 1; off < 256; off <<= 1) {
        int t = (threadIdx.x >= off) ? s[threadIdx.x - off] : 0;
        __syncthreads();
        s[threadIdx.x] += t;
        __syncthreads();
    }
    if (i < NN) g_scan[i] = s[threadIdx.x];          // inclusive
    if (threadIdx.x == 255) g_bsum[blockIdx.x] = s[255];
}

__global__ void k_scan2() {
    __shared__ int s[256];
    int v = (threadIdx.x < NB) ? g_bsum[threadIdx.x] : 0;
    s[threadIdx.x] = v;
    __syncthreads();
#pragma unroll
    for (int off = 1; off < 256; off <<= 1) {
        int t = (threadIdx.x >= off) ? s[threadIdx.x - off] : 0;
        __syncthreads();
        s[threadIdx.x] += t;
        __syncthreads();
    }
    if (threadIdx.x < NB) g_boff[threadIdx.x] = s[threadIdx.x] - v;  // exclusive
}

__global__ void k_scan3() {
    int i = blockIdx.x * 256 + threadIdx.x;
    if (i < NN) {
        int rp = g_scan[i] - g_deg[i] + g_boff[blockIdx.x];
        g_rowptr[i] = rp;
        g_cur[i] = rp;
    }
    if (i == 0) g_rowptr[NN] = NE;
}

// ---------------------------------------------------------------- CSR scatter
__global__ void k_scatter(const int* __restrict__ ei) {
    int e = blockIdx.x * blockDim.x + threadIdx.x;
    if (e >= NE) return;
    int s = ei[e];
    int d = ei[NE + e];
    int pos = atomicAdd(&g_cur[d], 1);
    g_cs[pos] = s;
    g_cw[pos] = g_dis[s] * g_dis[d];
}

// ---------------------------------------------------------------- tf32 helpers
__device__ __forceinline__ unsigned tf32_of(float x) {
    unsigned r;
    asm("cvt.rna.tf32.f32 %0, %1;" : "=r"(r) : "f"(x));
    return r;
}

__device__ __forceinline__ void tf32_split(float x, unsigned& hi, unsigned& lo) {
    hi = tf32_of(x);
    lo = tf32_of(x - __uint_as_float(hi));
}

__device__ __forceinline__ void mma_tf32(float* d, const unsigned* a, const unsigned* b) {
    asm("mma.sync.aligned.m16n8k8.row.col.f32.tf32.tf32.f32 "
        "{%0,%1,%2,%3}, {%4,%5,%6,%7}, {%8,%9}, {%0,%1,%2,%3};"
        : "+f"(d[0]), "+f"(d[1]), "+f"(d[2]), "+f"(d[3])
        : "r"(a[0]), "r"(a[1]), "r"(a[2]), "r"(a[3]), "r"(b[0]), "r"(b[1]));
}

// ---------------------------------------------------------------- 3xTF32 GEMM
// g_t[M,BN] = A[M,128] @ B[128,BN].  BM=128, BK=16, 8 warps (4m x 2n),
// warp tile 32 x BN/2, mma m16n8k8, hi/lo split for fp32-grade accuracy.
#define AST 20    // As row stride (floats)

template <int BN>
__global__ __launch_bounds__(256, 1) void gemm_tf32(
    const float* __restrict__ Aparam, const float* __restrict__ B,
    int M, int useH)
{
    const float* __restrict__ A = useH ? g_h : Aparam;

    constexpr int BST = BN + 8;
    constexpr int NT = BN / 16;           // n-tiles per warp (128->8, 64->4)
    constexpr int BLD = (16 * BN) / (256 * 4);  // B float4 loads per thread

    __shared__ float As[128 * AST];   // [m][k] m-major
    __shared__ float Bs[16 * BST];    // [k][n]

    const int tid = threadIdx.x;
    const int w = tid >> 5;
    const int lane = tid & 31;
    const int g = lane >> 2;        // 0..7
    const int tig = lane & 3;       // 0..3
    const int warp_m = (w & 3) * 32;
    const int warp_n = (w >> 2) * (BN / 2);
    const int m0 = blockIdx.y * 128;

    float acc[2][NT][4];
#pragma unroll
    for (int i = 0; i < 2; i++)
#pragma unroll
        for (int j = 0; j < NT; j++)
#pragma unroll
            for (int c = 0; c < 4; c++) acc[i][j][c] = 0.f;

    for (int k0 = 0; k0 < 128; k0 += 16) {
        // load A tile 128x16 (layout [m][k])
#pragma unroll
        for (int i = 0; i < 2; i++) {
            int idx = tid * 2 + i;            // 0..511
            int row = idx >> 2;               // 0..127
            int kc = (idx & 3) * 4;           // 0,4,8,12
            float4 av = make_float4(0.f, 0.f, 0.f, 0.f);
            if (m0 + row < M)
                av = *(const float4*)(A + (long long)(m0 + row) * 128 + k0 + kc);
            As[row * AST + kc + 0] = av.x;
            As[row * AST + kc + 1] = av.y;
            As[row * AST + kc + 2] = av.z;
            As[row * AST + kc + 3] = av.w;
        }
        // load B tile 16xBN
#pragma unroll
        for (int i = 0; i < BLD; i++) {
            int idx = tid * BLD + i;
            int row = idx / (BN / 4);
            int c4 = (idx % (BN / 4)) * 4;
            float4 bv = *(const float4*)(B + (long long)(k0 + row) * BN + c4);
            *(float4*)&Bs[row * BST + c4] = bv;
        }
        __syncthreads();

#pragma unroll
        for (int ks = 0; ks < 16; ks += 8) {
            unsigned ahi[2][4], alo[2][4];
#pragma unroll
            for (int mt = 0; mt < 2; mt++) {
                int base = warp_m + mt * 16;
                float a0 = As[(base + g) * AST + ks + tig];
                float a1 = As[(base + g + 8) * AST + ks + tig];
                float a2 = As[(base + g) * AST + ks + tig + 4];
                float a3 = As[(base + g + 8) * AST + ks + tig + 4];
                tf32_split(a0, ahi[mt][0], alo[mt][0]);
                tf32_split(a1, ahi[mt][1], alo[mt][1]);
                tf32_split(a2, ahi[mt][2], alo[mt][2]);
                tf32_split(a3, ahi[mt][3], alo[mt][3]);
            }
            unsigned bhi[NT][2], blo[NT][2];
#pragma unroll
            for (int nt = 0; nt < NT; nt++) {
                int col = warp_n + nt * 8 + g;
                float b0 = Bs[(ks + tig) * BST + col];
                float b1 = Bs[(ks + tig + 4) * BST + col];
                tf32_split(b0, bhi[nt][0], blo[nt][0]);
                tf32_split(b1, bhi[nt][1], blo[nt][1]);
            }
#pragma unroll
            for (int mt = 0; mt < 2; mt++)
#pragma unroll
                for (int nt = 0; nt < NT; nt++) {
                    mma_tf32(acc[mt][nt], alo[mt], bhi[nt]);
                    mma_tf32(acc[mt][nt], ahi[mt], blo[nt]);
                    mma_tf32(acc[mt][nt], ahi[mt], bhi[nt]);
                }
        }
        __syncthreads();
    }

#pragma unroll
    for (int mt = 0; mt < 2; mt++) {
#pragma unroll
        for (int half = 0; half < 2; half++) {
            int r = m0 + warp_m + mt * 16 + g + half * 8;
            if (r < M) {
#pragma unroll
                for (int nt = 0; nt < NT; nt++) {
                    int c = warp_n + nt * 8 + tig * 2;
                    float2 v = half ? make_float2(acc[mt][nt][2], acc[mt][nt][3])
                                    : make_float2(acc[mt][nt][0], acc[mt][nt][1]);
                    *(float2*)&g_t[(long long)r * BN + c] = v;
                }
            }
        }
    }
}

// ---------------------------------------------------------------- CSR aggregation (F=128)
// g_h[node] = relu( dis^2*t[node] + sum_e w_e * t[src_e] + bias )
// Index/weight loads are warp-uniform -> L1 broadcast; no smem staging.
__global__ __launch_bounds__(128) void k_agg128(const float* __restrict__ bias)
{
    const int node = blockIdx.x;
    const int tid  = threadIdx.x;
    const int beg = g_rowptr[node];
    const int end = g_rowptr[node + 1];
    const float ds = g_dis[node];

    float acc = ds * ds * g_t[(long long)node * 128 + tid];

    int j = beg;
    for (; j + 4 <= end; j += 4) {
        int   s0 = g_cs[j + 0], s1 = g_cs[j + 1], s2 = g_cs[j + 2], s3 = g_cs[j + 3];
        float w0 = g_cw[j + 0], w1 = g_cw[j + 1], w2 = g_cw[j + 2], w3 = g_cw[j + 3];
        float v0 = g_t[(long long)s0 * 128 + tid];
        float v1 = g_t[(long long)s1 * 128 + tid];
        float v2 = g_t[(long long)s2 * 128 + tid];
        float v3 = g_t[(long long)s3 * 128 + tid];
        acc += w0 * v0 + w1 * v1 + w2 * v2 + w3 * v3;
    }
    for (; j < end; j++)
        acc += g_cw[j] * g_t[(long long)g_cs[j] * 128 + tid];

    g_h[(long long)node * 128 + tid] = fmaxf(acc + bias[tid], 0.f);
}

// ---------------------------------------------------------------- fused layer-3 agg + readout
__global__ __launch_bounds__(64) void k_final64(
    const float* __restrict__ b2,
    const float* __restrict__ Wout,
    const float* __restrict__ bout,
    float* __restrict__ out)
{
    __shared__ float s_part[2];
    const int node = blockIdx.x;
    const int tid  = threadIdx.x;
    const int beg = g_rowptr[node];
    const int end = g_rowptr[node + 1];
    const float ds = g_dis[node];

    float acc = ds * ds * g_t[(long long)node * 64 + tid];

    int j = beg;
    for (; j + 4 <= end; j += 4) {
        int   s0 = g_cs[j + 0], s1 = g_cs[j + 1], s2 = g_cs[j + 2], s3 = g_cs[j + 3];
        float w0 = g_cw[j + 0], w1 = g_cw[j + 1], w2 = g_cw[j + 2], w3 = g_cw[j + 3];
        float v0 = g_t[(long long)s0 * 64 + tid];
        float v1 = g_t[(long long)s1 * 64 + tid];
        float v2 = g_t[(long long)s2 * 64 + tid];
        float v3 = g_t[(long long)s3 * 64 + tid];
        acc += w0 * v0 + w1 * v1 + w2 * v2 + w3 * v3;
    }
    for (; j < end; j++)
        acc += g_cw[j] * g_t[(long long)g_cs[j] * 64 + tid];

    float v = acc + b2[tid];
    out[NN + (long long)node * 64 + tid] = v;

    float p = v * Wout[tid];
#pragma unroll
    for (int o = 16; o; o >>= 1) p += __shfl_down_sync(0xFFFFFFFFu, p, o);
    if ((tid & 31) == 0) s_part[tid >> 5] = p;
    __syncthreads();
    if (tid == 0) out[node] = s_part[0] + s_part[1] + bout[0];
}

// ---------------------------------------------------------------- launcher
extern "C" void kernel_launch(void* const* d_in, const int* in_sizes, int n_in,
                              void* d_out, int out_size)
{
    const float* x    = (const float*)d_in[0];
    const int*   ei   = (const int*)d_in[1];     // int32 (JAX x64 disabled)
    const float* W1   = (const float*)d_in[2];
    const float* b1   = (const float*)d_in[3];
    const float* Wh   = (const float*)d_in[4];
    const float* bh   = (const float*)d_in[5];
    const float* W2   = (const float*)d_in[6];
    const float* b2   = (const float*)d_in[7];
    const float* Wout = (const float*)d_in[8];
    const float* bout = (const float*)d_in[9];
    float*       out  = (float*)d_out;

    // Fork: CSR build runs concurrently with layer-1 GEMM (captured as graph branch).
    cudaStream_t s2;
    cudaEvent_t ev_fork, ev_join;
    cudaStreamCreate(&s2);
    cudaEventCreate(&ev_fork);
    cudaEventCreate(&ev_join);

    cudaEventRecord(ev_fork, 0);
    cudaStreamWaitEvent(s2, ev_fork, 0);

    // ---- branch A (s2): normalization + CSR build
    k_deg_init<<<cdiv(NN, 256), 256, 0, s2>>>();
    k_deg_count<<<cdiv(NE, 256), 256, 0, s2>>>(ei);
    k_scan1<<<NB, 256, 0, s2>>>();
    k_scan2<<<1, 256, 0, s2>>>();
    k_scan3<<<NB, 256, 0, s2>>>();
    k_scatter<<<cdiv(NE, 256), 256, 0, s2>>>(ei);
    cudaEventRecord(ev_join, s2);

    // ---- branch B (default stream): layer-1 GEMM
    dim3 gt(1, cdiv(NN, 128));
    gemm_tf32<128><<<gt, 256>>>(x, W1, NN, 0);

    // join
    cudaStreamWaitEvent(0, ev_join, 0);

    // layer 1 aggregation
    k_agg128<<<NN, 128>>>(b1);
    // layer 2
    gemm_tf32<128><<<gt, 256>>>(nullptr, Wh, NN, 1);
    k_agg128<<<NN, 128>>>(bh);
    // layer 3 (128 -> 64) + fused readout
    gemm_tf32<64><<<gt, 256>>>(nullptr, W2, NN, 1);
    k_final64<<<NN, 64>>>(b2, Wout, bout, out);
}

// round 7
// speedup vs baseline: 3.2866x; 1.2007x over previous
#include <cuda_runtime.h>
#include <cuda_fp16.h>

#define NN 50000
#define NE 800000
#define NB 196              // cdiv(NN,256)

// Scratch (device globals; no allocation allowed)
__device__ float   g_dis[NN];
__device__ int     g_deg[NN];
__device__ int     g_scan[NN];
__device__ int     g_bsum[256];
__device__ int     g_boff[256];
__device__ int     g_rowptr[NN + 1];
__device__ int     g_cur[NN];
__device__ int     g_cs[NE];            // CSR src ids (grouped by dst)
__device__ float   g_cw[NE];            // CSR edge weights dis[s]*dis[d]
__device__ __half2 g_t16[NN * 64];      // linear-transform output (fp16, max F=128)
__device__ float   g_h[NN * 128];       // post-activation features (fp32)

static inline int cdiv(int a, int b) { return (a + b - 1) / b; }

// ---------------------------------------------------------------- degree
__global__ void k_deg_init() {
    int i = blockIdx.x * blockDim.x + threadIdx.x;
    if (i < NN) g_deg[i] = 0;
}

__global__ void k_deg_count(const int* __restrict__ ei) {
    int e = blockIdx.x * blockDim.x + threadIdx.x;
    if (e < NE) atomicAdd(&g_deg[ei[NE + e]], 1);
}

// ---------------------------------------------------------------- scan (3-kernel)
__global__ void k_scan1() {
    __shared__ int s[256];
    int i = blockIdx.x * 256 + threadIdx.x;
    int v = (i < NN) ? g_deg[i] : 0;
    if (i < NN) g_dis[i] = rsqrtf(1.0f + (float)v);
    s[threadIdx.x] = v;
    __syncthreads();
#pragma unroll
    for (int off = 1; off < 256; off <<= 1) {
        int t = (threadIdx.x >= off) ? s[threadIdx.x - off] : 0;
        __syncthreads();
        s[threadIdx.x] += t;
        __syncthreads();
    }
    if (i < NN) g_scan[i] = s[threadIdx.x];          // inclusive
    if (threadIdx.x == 255) g_bsum[blockIdx.x] = s[255];
}

__global__ void k_scan2() {
    __shared__ int s[256];
    int v = (threadIdx.x < NB) ? g_bsum[threadIdx.x] : 0;
    s[threadIdx.x] = v;
    __syncthreads();
#pragma unroll
    for (int off = 1; off < 256; off <<= 1) {
        int t = (threadIdx.x >= off) ? s[threadIdx.x - off] : 0;
        __syncthreads();
        s[threadIdx.x] += t;
        __syncthreads();
    }
    if (threadIdx.x < NB) g_boff[threadIdx.x] = s[threadIdx.x] - v;  // exclusive
}

__global__ void k_scan3() {
    int i = blockIdx.x * 256 + threadIdx.x;
    if (i < NN) {
        int rp = g_scan[i] - g_deg[i] + g_boff[blockIdx.x];
        g_rowptr[i] = rp;
        g_cur[i] = rp;
    }
    if (i == 0) g_rowptr[NN] = NE;
}

// ---------------------------------------------------------------- CSR scatter
__global__ void k_scatter(const int* __restrict__ ei) {
    int e = blockIdx.x * blockDim.x + threadIdx.x;
    if (e >= NE) return;
    int s = ei[e];
    int d = ei[NE + e];
    int pos = atomicAdd(&g_cur[d], 1);
    g_cs[pos] = s;
    g_cw[pos] = g_dis[s] * g_dis[d];
}

// ---------------------------------------------------------------- tf32 helpers
__device__ __forceinline__ unsigned tf32_of(float x) {
    unsigned r;
    asm("cvt.rna.tf32.f32 %0, %1;" : "=r"(r) : "f"(x));
    return r;
}

__device__ __forceinline__ void tf32_split(float x, unsigned& hi, unsigned& lo) {
    hi = tf32_of(x);
    lo = tf32_of(x - __uint_as_float(hi));
}

__device__ __forceinline__ void mma_tf32(float* d, const unsigned* a, const unsigned* b) {
    asm("mma.sync.aligned.m16n8k8.row.col.f32.tf32.tf32.f32 "
        "{%0,%1,%2,%3}, {%4,%5,%6,%7}, {%8,%9}, {%0,%1,%2,%3};"
        : "+f"(d[0]), "+f"(d[1]), "+f"(d[2]), "+f"(d[3])
        : "r"(a[0]), "r"(a[1]), "r"(a[2]), "r"(a[3]), "r"(b[0]), "r"(b[1]));
}

// ---------------------------------------------------------------- 3xTF32 GEMM
// g_t16[M,BN] = fp16( A[M,128] @ B[128,BN] ).  BM=128, BK=16, 8 warps (4m x 2n).
#define AST 20    // As row stride (floats)

template <int BN>
__global__ __launch_bounds__(256, 1) void gemm_tf32(
    const float* __restrict__ Aparam, const float* __restrict__ B,
    int M, int useH)
{
    const float* __restrict__ A = useH ? g_h : Aparam;

    constexpr int BST = BN + 8;
    constexpr int NT = BN / 16;                 // n-tiles per warp
    constexpr int BLD = (16 * BN) / (256 * 4);  // B float4 loads per thread

    __shared__ float As[128 * AST];   // [m][k]
    __shared__ float Bs[16 * BST];    // [k][n]

    const int tid = threadIdx.x;
    const int w = tid >> 5;
    const int lane = tid & 31;
    const int g = lane >> 2;        // 0..7
    const int tig = lane & 3;       // 0..3
    const int warp_m = (w & 3) * 32;
    const int warp_n = (w >> 2) * (BN / 2);
    const int m0 = blockIdx.y * 128;

    float acc[2][NT][4];
#pragma unroll
    for (int i = 0; i < 2; i++)
#pragma unroll
        for (int j = 0; j < NT; j++)
#pragma unroll
            for (int c = 0; c < 4; c++) acc[i][j][c] = 0.f;

    for (int k0 = 0; k0 < 128; k0 += 16) {
#pragma unroll
        for (int i = 0; i < 2; i++) {
            int idx = tid * 2 + i;
            int row = idx >> 2;
            int kc = (idx & 3) * 4;
            float4 av = make_float4(0.f, 0.f, 0.f, 0.f);
            if (m0 + row < M)
                av = *(const float4*)(A + (long long)(m0 + row) * 128 + k0 + kc);
            As[row * AST + kc + 0] = av.x;
            As[row * AST + kc + 1] = av.y;
            As[row * AST + kc + 2] = av.z;
            As[row * AST + kc + 3] = av.w;
        }
#pragma unroll
        for (int i = 0; i < BLD; i++) {
            int idx = tid * BLD + i;
            int row = idx / (BN / 4);
            int c4 = (idx % (BN / 4)) * 4;
            float4 bv = *(const float4*)(B + (long long)(k0 + row) * BN + c4);
            *(float4*)&Bs[row * BST + c4] = bv;
        }
        __syncthreads();

#pragma unroll
        for (int ks = 0; ks < 16; ks += 8) {
            unsigned ahi[2][4], alo[2][4];
#pragma unroll
            for (int mt = 0; mt < 2; mt++) {
                int base = warp_m + mt * 16;
                float a0 = As[(base + g) * AST + ks + tig];
                float a1 = As[(base + g + 8) * AST + ks + tig];
                float a2 = As[(base + g) * AST + ks + tig + 4];
                float a3 = As[(base + g + 8) * AST + ks + tig + 4];
                tf32_split(a0, ahi[mt][0], alo[mt][0]);
                tf32_split(a1, ahi[mt][1], alo[mt][1]);
                tf32_split(a2, ahi[mt][2], alo[mt][2]);
                tf32_split(a3, ahi[mt][3], alo[mt][3]);
            }
            unsigned bhi[NT][2], blo[NT][2];
#pragma unroll
            for (int nt = 0; nt < NT; nt++) {
                int col = warp_n + nt * 8 + g;
                float b0 = Bs[(ks + tig) * BST + col];
                float b1 = Bs[(ks + tig + 4) * BST + col];
                tf32_split(b0, bhi[nt][0], blo[nt][0]);
                tf32_split(b1, bhi[nt][1], blo[nt][1]);
            }
#pragma unroll
            for (int mt = 0; mt < 2; mt++)
#pragma unroll
                for (int nt = 0; nt < NT; nt++) {
                    mma_tf32(acc[mt][nt], alo[mt], bhi[nt]);
                    mma_tf32(acc[mt][nt], ahi[mt], blo[nt]);
                    mma_tf32(acc[mt][nt], ahi[mt], bhi[nt]);
                }
        }
        __syncthreads();
    }

    // epilogue: write fp16 pairs (c even -> half2-aligned)
#pragma unroll
    for (int mt = 0; mt < 2; mt++) {
#pragma unroll
        for (int half = 0; half < 2; half++) {
            int r = m0 + warp_m + mt * 16 + g + half * 8;
            if (r < M) {
#pragma unroll
                for (int nt = 0; nt < NT; nt++) {
                    int c = warp_n + nt * 8 + tig * 2;
                    float2 v = half ? make_float2(acc[mt][nt][2], acc[mt][nt][3])
                                    : make_float2(acc[mt][nt][0], acc[mt][nt][1]);
                    g_t16[(long long)r * (BN / 2) + (c >> 1)] = __floats2half2_rn(v.x, v.y);
                }
            }
        }
    }
}

// ---------------------------------------------------------------- CSR aggregation (F=128)
// 64 threads/node, each owns 2 features (half2 lane).
// g_h[node] = relu( dis^2*t[node] + sum_e w_e * t[src_e] + bias )
__global__ __launch_bounds__(64) void k_agg128(const float* __restrict__ bias)
{
    const int node = blockIdx.x;
    const int tid  = threadIdx.x;          // 0..63
    const int beg = g_rowptr[node];
    const int end = g_rowptr[node + 1];
    const float ds = g_dis[node];

    float2 self = __half22float2(g_t16[(long long)node * 64 + tid]);
    float ax = ds * ds * self.x;
    float ay = ds * ds * self.y;

    int j = beg;
    for (; j + 4 <= end; j += 4) {
        int   s0 = g_cs[j + 0], s1 = g_cs[j + 1], s2 = g_cs[j + 2], s3 = g_cs[j + 3];
        float w0 = g_cw[j + 0], w1 = g_cw[j + 1], w2 = g_cw[j + 2], w3 = g_cw[j + 3];
        float2 v0 = __half22float2(g_t16[(long long)s0 * 64 + tid]);
        float2 v1 = __half22float2(g_t16[(long long)s1 * 64 + tid]);
        float2 v2 = __half22float2(g_t16[(long long)s2 * 64 + tid]);
        float2 v3 = __half22float2(g_t16[(long long)s3 * 64 + tid]);
        ax += w0 * v0.x + w1 * v1.x + w2 * v2.x + w3 * v3.x;
        ay += w0 * v0.y + w1 * v1.y + w2 * v2.y + w3 * v3.y;
    }
    for (; j < end; j++) {
        float w = g_cw[j];
        float2 v = __half22float2(g_t16[(long long)g_cs[j] * 64 + tid]);
        ax += w * v.x;
        ay += w * v.y;
    }

    float2 bb = *(const float2*)&bias[tid * 2];
    float2 o = make_float2(fmaxf(ax + bb.x, 0.f), fmaxf(ay + bb.y, 0.f));
    *(float2*)&g_h[(long long)node * 128 + tid * 2] = o;
}

// ---------------------------------------------------------------- fused layer-3 agg + readout (F=64)
// 32 threads/node, each owns 2 features.
__global__ __launch_bounds__(32) void k_final64(
    const float* __restrict__ b2,
    const float* __restrict__ Wout,
    const float* __restrict__ bout,
    float* __restrict__ out)
{
    const int node = blockIdx.x;
    const int tid  = threadIdx.x;          // 0..31
    const int beg = g_rowptr[node];
    const int end = g_rowptr[node + 1];
    const float ds = g_dis[node];

    float2 self = __half22float2(g_t16[(long long)node * 32 + tid]);
    float ax = ds * ds * self.x;
    float ay = ds * ds * self.y;

    int j = beg;
    for (; j + 4 <= end; j += 4) {
        int   s0 = g_cs[j + 0], s1 = g_cs[j + 1], s2 = g_cs[j + 2], s3 = g_cs[j + 3];
        float w0 = g_cw[j + 0], w1 = g_cw[j + 1], w2 = g_cw[j + 2], w3 = g_cw[j + 3];
        float2 v0 = __half22float2(g_t16[(long long)s0 * 32 + tid]);
        float2 v1 = __half22float2(g_t16[(long long)s1 * 32 + tid]);
        float2 v2 = __half22float2(g_t16[(long long)s2 * 32 + tid]);
        float2 v3 = __half22float2(g_t16[(long long)s3 * 32 + tid]);
        ax += w0 * v0.x + w1 * v1.x + w2 * v2.x + w3 * v3.x;
        ay += w0 * v0.y + w1 * v1.y + w2 * v2.y + w3 * v3.y;
    }
    for (; j < end; j++) {
        float w = g_cw[j];
        float2 v = __half22float2(g_t16[(long long)g_cs[j] * 32 + tid]);
        ax += w * v.x;
        ay += w * v.y;
    }

    float2 bb = *(const float2*)&b2[tid * 2];
    float vx = ax + bb.x;
    float vy = ay + bb.y;
    *(float2*)&out[NN + (long long)node * 64 + tid * 2] = make_float2(vx, vy);

    float2 ww = *(const float2*)&Wout[tid * 2];
    float p = vx * ww.x + vy * ww.y;
#pragma unroll
    for (int o = 16; o; o >>= 1) p += __shfl_down_sync(0xFFFFFFFFu, p, o);
    if (tid == 0) out[node] = p + bout[0];
}

// ---------------------------------------------------------------- launcher
extern "C" void kernel_launch(void* const* d_in, const int* in_sizes, int n_in,
                              void* d_out, int out_size)
{
    const float* x    = (const float*)d_in[0];
    const int*   ei   = (const int*)d_in[1];     // int32 (JAX x64 disabled)
    const float* W1   = (const float*)d_in[2];
    const float* b1   = (const float*)d_in[3];
    const float* Wh   = (const float*)d_in[4];
    const float* bh   = (const float*)d_in[5];
    const float* W2   = (const float*)d_in[6];
    const float* b2   = (const float*)d_in[7];
    const float* Wout = (const float*)d_in[8];
    const float* bout = (const float*)d_in[9];
    float*       out  = (float*)d_out;

    // Fork: CSR build runs concurrently with layer-1 GEMM (graph branch).
    cudaStream_t s2;
    cudaEvent_t ev_fork, ev_join;
    cudaStreamCreate(&s2);
    cudaEventCreate(&ev_fork);
    cudaEventCreate(&ev_join);

    cudaEventRecord(ev_fork, 0);
    cudaStreamWaitEvent(s2, ev_fork, 0);

    // ---- branch A (s2): normalization + CSR build
    k_deg_init<<<cdiv(NN, 256), 256, 0, s2>>>();
    k_deg_count<<<cdiv(NE, 256), 256, 0, s2>>>(ei);
    k_scan1<<<NB, 256, 0, s2>>>();
    k_scan2<<<1, 256, 0, s2>>>();
    k_scan3<<<NB, 256, 0, s2>>>();
    k_scatter<<<cdiv(NE, 256), 256, 0, s2>>>(ei);
    cudaEventRecord(ev_join, s2);

    // ---- branch B (default stream): layer-1 GEMM
    dim3 gt(1, cdiv(NN, 128));
    gemm_tf32<128><<<gt, 256>>>(x, W1, NN, 0);

    // join
    cudaStreamWaitEvent(0, ev_join, 0);

    // layer 1 aggregation
    k_agg128<<<NN, 64>>>(b1);
    // layer 2
    gemm_tf32<128><<<gt, 256>>>(nullptr, Wh, NN, 1);
    k_agg128<<<NN, 64>>>(bh);
    // layer 3 (128 -> 64) + fused readout
    gemm_tf32<64><<<gt, 256>>>(nullptr, W2, NN, 1);
    k_final64<<<NN, 32>>>(b2, Wout, bout, out);
}

// round 8
// speedup vs baseline: 3.7141x; 1.1301x over previous
#include <cuda_runtime.h>
#include <cuda_fp16.h>

#define NN 50000
#define NE 800000
#define NB 196              // cdiv(NN,256)

// Scratch (device globals; no allocation allowed)
__device__ float   g_dis[NN];
__device__ int     g_deg[NN];
__device__ int     g_scan[NN];
__device__ int     g_bsum[256];
__device__ int     g_boff[256];
__device__ int     g_rowptr[NN + 1];
__device__ int     g_cur[NN];
__device__ int     g_cs[NE];            // CSR src ids (grouped by dst)
__device__ float   g_cw[NE];            // CSR edge weights dis[s]*dis[d]
__device__ __half2 g_t16[NN * 64];      // linear-transform output (fp16)
__device__ __half2 g_h16[NN * 64];      // post-activation features (fp16)

static inline int cdiv(int a, int b) { return (a + b - 1) / b; }

// ---------------------------------------------------------------- degree
__global__ void k_deg_init() {
    int i = blockIdx.x * blockDim.x + threadIdx.x;
    if (i < NN) g_deg[i] = 0;
}

__global__ void k_deg_count(const int* __restrict__ ei) {
    int e = blockIdx.x * blockDim.x + threadIdx.x;
    if (e < NE) atomicAdd(&g_deg[ei[NE + e]], 1);
}

// ---------------------------------------------------------------- scan (3-kernel)
__global__ void k_scan1() {
    __shared__ int s[256];
    int i = blockIdx.x * 256 + threadIdx.x;
    int v = (i < NN) ? g_deg[i] : 0;
    if (i < NN) g_dis[i] = rsqrtf(1.0f + (float)v);
    s[threadIdx.x] = v;
    __syncthreads();
#pragma unroll
    for (int off = 1; off < 256; off <<= 1) {
        int t = (threadIdx.x >= off) ? s[threadIdx.x - off] : 0;
        __syncthreads();
        s[threadIdx.x] += t;
        __syncthreads();
    }
    if (i < NN) g_scan[i] = s[threadIdx.x];          // inclusive
    if (threadIdx.x == 255) g_bsum[blockIdx.x] = s[255];
}

__global__ void k_scan2() {
    __shared__ int s[256];
    int v = (threadIdx.x < NB) ? g_bsum[threadIdx.x] : 0;
    s[threadIdx.x] = v;
    __syncthreads();
#pragma unroll
    for (int off = 1; off < 256; off <<= 1) {
        int t = (threadIdx.x >= off) ? s[threadIdx.x - off] : 0;
        __syncthreads();
        s[threadIdx.x] += t;
        __syncthreads();
    }
    if (threadIdx.x < NB) g_boff[threadIdx.x] = s[threadIdx.x] - v;  // exclusive
}

__global__ void k_scan3() {
    int i = blockIdx.x * 256 + threadIdx.x;
    if (i < NN) {
        int rp = g_scan[i] - g_deg[i] + g_boff[blockIdx.x];
        g_rowptr[i] = rp;
        g_cur[i] = rp;
    }
    if (i == 0) g_rowptr[NN] = NE;
}

// ---------------------------------------------------------------- CSR scatter
__global__ void k_scatter(const int* __restrict__ ei) {
    int e = blockIdx.x * blockDim.x + threadIdx.x;
    if (e >= NE) return;
    int s = ei[e];
    int d = ei[NE + e];
    int pos = atomicAdd(&g_cur[d], 1);
    g_cs[pos] = s;
    g_cw[pos] = g_dis[s] * g_dis[d];
}

// ---------------------------------------------------------------- fp16 MMA
__device__ __forceinline__ void mma_f16(float* d, const unsigned* a, const unsigned* b) {
    asm("mma.sync.aligned.m16n8k16.row.col.f32.f16.f16.f32 "
        "{%0,%1,%2,%3}, {%4,%5,%6,%7}, {%8,%9}, {%0,%1,%2,%3};"
        : "+f"(d[0]), "+f"(d[1]), "+f"(d[2]), "+f"(d[3])
        : "r"(a[0]), "r"(a[1]), "r"(a[2]), "r"(a[3]), "r"(b[0]), "r"(b[1]));
}

// ---------------------------------------------------------------- fp16 GEMM
// g_t16[M,BN] = fp16( A[M,128] @ B[128,BN] ), fp32 accumulate.
// BM=128, BK=16, 8 warps (4m x 2n), warp tile 32 x BN/2, mma m16n8k16.
// A: fp32 global (layer 1) or g_h16. B: fp32 global, converted per tile.
#define ASTH 24   // As row stride (halves): conflict-free fragment loads

template <int BN>
__global__ __launch_bounds__(256, 1) void gemm_f16(
    const float* __restrict__ Aparam, const float* __restrict__ B,
    int M, int useH)
{
    __shared__ __half As[128 * ASTH];   // [m][k]
    __shared__ __half Bt[BN * ASTH];    // [n][k] (transposed)

    const int tid = threadIdx.x;
    const int w = tid >> 5;
    const int lane = tid & 31;
    const int g = lane >> 2;        // 0..7
    const int tig = lane & 3;       // 0..3
    const int warp_m = (w & 3) * 32;
    const int warp_n = (w >> 2) * (BN / 2);
    const int m0 = blockIdx.y * 128;

    constexpr int NT = BN / 16;     // n-tiles per warp
    __half2* As2 = (__half2*)As;
    __half2* Bt2 = (__half2*)Bt;

    float acc[2][NT][4];
#pragma unroll
    for (int i = 0; i < 2; i++)
#pragma unroll
        for (int j = 0; j < NT; j++)
#pragma unroll
            for (int c = 0; c < 4; c++) acc[i][j][c] = 0.f;

    for (int k0 = 0; k0 < 128; k0 += 16) {
        // ---- load A tile 128x16 halves
        if (useH) {
            int row = tid >> 1;                 // 0..127
            int part = tid & 1;                 // 8 halves each
            uint4 v = make_uint4(0, 0, 0, 0);
            if (m0 + row < M)
                v = *(const uint4*)(g_h16 + (long long)(m0 + row) * 64 + (k0 >> 1) + part * 4);
            *(uint4*)&As[row * ASTH + part * 8] = v;
        } else {
#pragma unroll
            for (int i = 0; i < 2; i++) {
                int idx = tid * 2 + i;          // 0..511
                int row = idx >> 2;             // 0..127
                int kc = (idx & 3) * 4;         // 0,4,8,12
                float4 av = make_float4(0.f, 0.f, 0.f, 0.f);
                if (m0 + row < M)
                    av = *(const float4*)(Aparam + (long long)(m0 + row) * 128 + k0 + kc);
                As2[(row * ASTH + kc) >> 1] = __floats2half2_rn(av.x, av.y);
                As2[(row * ASTH + kc + 2) >> 1] = __floats2half2_rn(av.z, av.w);
            }
        }
        // ---- load B tile 16xBN fp32, store transposed [n][k] as fp16
        constexpr int BLD = (16 * BN) / (256 * 4);
#pragma unroll
        for (int i = 0; i < BLD; i++) {
            int idx = tid * BLD + i;
            int row = idx / (BN / 4);           // k in 0..15
            int c4 = (idx % (BN / 4)) * 4;      // n
            float4 bv = *(const float4*)(B + (long long)(k0 + row) * BN + c4);
            Bt[(c4 + 0) * ASTH + row] = __float2half_rn(bv.x);
            Bt[(c4 + 1) * ASTH + row] = __float2half_rn(bv.y);
            Bt[(c4 + 2) * ASTH + row] = __float2half_rn(bv.z);
            Bt[(c4 + 3) * ASTH + row] = __float2half_rn(bv.w);
        }
        __syncthreads();

        // ---- fragments + mma (one m16n8k16 per tile pair)
        unsigned a[2][4];
#pragma unroll
        for (int mt = 0; mt < 2; mt++) {
            int r0 = warp_m + mt * 16 + g;
            a[mt][0] = *(unsigned*)&As2[r0 * (ASTH / 2) + tig];
            a[mt][1] = *(unsigned*)&As2[(r0 + 8) * (ASTH / 2) + tig];
            a[mt][2] = *(unsigned*)&As2[r0 * (ASTH / 2) + tig + 4];
            a[mt][3] = *(unsigned*)&As2[(r0 + 8) * (ASTH / 2) + tig + 4];
        }
#pragma unroll
        for (int nt = 0; nt < NT; nt++) {
            int col = warp_n + nt * 8 + g;
            unsigned b[2];
            b[0] = *(unsigned*)&Bt2[col * (ASTH / 2) + tig];
            b[1] = *(unsigned*)&Bt2[col * (ASTH / 2) + tig + 4];
#pragma unroll
            for (int mt = 0; mt < 2; mt++)
                mma_f16(acc[mt][nt], a[mt], b);
        }
        __syncthreads();
    }

    // epilogue: write fp16 pairs
#pragma unroll
    for (int mt = 0; mt < 2; mt++) {
#pragma unroll
        for (int half = 0; half < 2; half++) {
            int r = m0 + warp_m + mt * 16 + g + half * 8;
            if (r < M) {
#pragma unroll
                for (int nt = 0; nt < NT; nt++) {
                    int c = warp_n + nt * 8 + tig * 2;
                    float2 v = half ? make_float2(acc[mt][nt][2], acc[mt][nt][3])
                                    : make_float2(acc[mt][nt][0], acc[mt][nt][1]);
                    g_t16[(long long)r * (BN / 2) + (c >> 1)] = __floats2half2_rn(v.x, v.y);
                }
            }
        }
    }
}

// ---------------------------------------------------------------- CSR aggregation (F=128)
// 64 threads/node, each owns 2 features; fp32 accumulate, fp16 store.
__global__ __launch_bounds__(64) void k_agg128(const float* __restrict__ bias)
{
    const int node = blockIdx.x;
    const int tid  = threadIdx.x;          // 0..63
    const int beg = g_rowptr[node];
    const int end = g_rowptr[node + 1];
    const float ds = g_dis[node];

    float2 self = __half22float2(g_t16[(long long)node * 64 + tid]);
    float ax = ds * ds * self.x;
    float ay = ds * ds * self.y;

    int j = beg;
    for (; j + 4 <= end; j += 4) {
        int   s0 = g_cs[j + 0], s1 = g_cs[j + 1], s2 = g_cs[j + 2], s3 = g_cs[j + 3];
        float w0 = g_cw[j + 0], w1 = g_cw[j + 1], w2 = g_cw[j + 2], w3 = g_cw[j + 3];
        float2 v0 = __half22float2(g_t16[(long long)s0 * 64 + tid]);
        float2 v1 = __half22float2(g_t16[(long long)s1 * 64 + tid]);
        float2 v2 = __half22float2(g_t16[(long long)s2 * 64 + tid]);
        float2 v3 = __half22float2(g_t16[(long long)s3 * 64 + tid]);
        ax += w0 * v0.x + w1 * v1.x + w2 * v2.x + w3 * v3.x;
        ay += w0 * v0.y + w1 * v1.y + w2 * v2.y + w3 * v3.y;
    }
    for (; j < end; j++) {
        float w = g_cw[j];
        float2 v = __half22float2(g_t16[(long long)g_cs[j] * 64 + tid]);
        ax += w * v.x;
        ay += w * v.y;
    }

    float2 bb = *(const float2*)&bias[tid * 2];
    g_h16[(long long)node * 64 + tid] =
        __floats2half2_rn(fmaxf(ax + bb.x, 0.f), fmaxf(ay + bb.y, 0.f));
}

// ---------------------------------------------------------------- fused layer-3 agg + readout (F=64)
__global__ __launch_bounds__(32) void k_final64(
    const float* __restrict__ b2,
    const float* __restrict__ Wout,
    const float* __restrict__ bout,
    float* __restrict__ out)
{
    const int node = blockIdx.x;
    const int tid  = threadIdx.x;          // 0..31
    const int beg = g_rowptr[node];
    const int end = g_rowptr[node + 1];
    const float ds = g_dis[node];

    float2 self = __half22float2(g_t16[(long long)node * 32 + tid]);
    float ax = ds * ds * self.x;
    float ay = ds * ds * self.y;

    int j = beg;
    for (; j + 4 <= end; j += 4) {
        int   s0 = g_cs[j + 0], s1 = g_cs[j + 1], s2 = g_cs[j + 2], s3 = g_cs[j + 3];
        float w0 = g_cw[j + 0], w1 = g_cw[j + 1], w2 = g_cw[j + 2], w3 = g_cw[j + 3];
        float2 v0 = __half22float2(g_t16[(long long)s0 * 32 + tid]);
        float2 v1 = __half22float2(g_t16[(long long)s1 * 32 + tid]);
        float2 v2 = __half22float2(g_t16[(long long)s2 * 32 + tid]);
        float2 v3 = __half22float2(g_t16[(long long)s3 * 32 + tid]);
        ax += w0 * v0.x + w1 * v1.x + w2 * v2.x + w3 * v3.x;
        ay += w0 * v0.y + w1 * v1.y + w2 * v2.y + w3 * v3.y;
    }
    for (; j < end; j++) {
        float w = g_cw[j];
        float2 v = __half22float2(g_t16[(long long)g_cs[j] * 32 + tid]);
        ax += w * v.x;
        ay += w * v.y;
    }

    float2 bb = *(const float2*)&b2[tid * 2];
    float vx = ax + bb.x;
    float vy = ay + bb.y;
    *(float2*)&out[NN + (long long)node * 64 + tid * 2] = make_float2(vx, vy);

    float2 ww = *(const float2*)&Wout[tid * 2];
    float p = vx * ww.x + vy * ww.y;
#pragma unroll
    for (int o = 16; o; o >>= 1) p += __shfl_down_sync(0xFFFFFFFFu, p, o);
    if (tid == 0) out[node] = p + bout[0];
}

// ---------------------------------------------------------------- launcher
extern "C" void kernel_launch(void* const* d_in, const int* in_sizes, int n_in,
                              void* d_out, int out_size)
{
    const float* x    = (const float*)d_in[0];
    const int*   ei   = (const int*)d_in[1];     // int32 (JAX x64 disabled)
    const float* W1   = (const float*)d_in[2];
    const float* b1   = (const float*)d_in[3];
    const float* Wh   = (const float*)d_in[4];
    const float* bh   = (const float*)d_in[5];
    const float* W2   = (const float*)d_in[6];
    const float* b2   = (const float*)d_in[7];
    const float* Wout = (const float*)d_in[8];
    const float* bout = (const float*)d_in[9];
    float*       out  = (float*)d_out;

    // Fork: CSR build runs concurrently with layer-1 GEMM (graph branch).
    cudaStream_t s2;
    cudaEvent_t ev_fork, ev_join;
    cudaStreamCreate(&s2);
    cudaEventCreate(&ev_fork);
    cudaEventCreate(&ev_join);

    cudaEventRecord(ev_fork, 0);
    cudaStreamWaitEvent(s2, ev_fork, 0);

    // ---- branch A (s2): normalization + CSR build
    k_deg_init<<<cdiv(NN, 256), 256, 0, s2>>>();
    k_deg_count<<<cdiv(NE, 256), 256, 0, s2>>>(ei);
    k_scan1<<<NB, 256, 0, s2>>>();
    k_scan2<<<1, 256, 0, s2>>>();
    k_scan3<<<NB, 256, 0, s2>>>();
    k_scatter<<<cdiv(NE, 256), 256, 0, s2>>>(ei);
    cudaEventRecord(ev_join, s2);

    // ---- branch B (default stream): layer-1 GEMM
    dim3 gt(1, cdiv(NN, 128));
    gemm_f16<128><<<gt, 256>>>(x, W1, NN, 0);

    // join
    cudaStreamWaitEvent(0, ev_join, 0);

    // layer 1 aggregation
    k_agg128<<<NN, 64>>>(b1);
    // layer 2
    gemm_f16<128><<<gt, 256>>>(nullptr, Wh, NN, 1);
    k_agg128<<<NN, 64>>>(bh);
    // layer 3 (128 -> 64) + fused readout
    gemm_f16<64><<<gt, 256>>>(nullptr, W2, NN, 1);
    k_final64<<<NN, 32>>>(b2, Wout, bout, out);
}

// round 9
// speedup vs baseline: 3.7666x; 1.0141x over previous
#include <cuda_runtime.h>
#include <cuda_fp16.h>

#define NN 50000
#define NE 800000
#define NB 196              // cdiv(NN,256)

// Scratch (device globals; no allocation allowed)
__device__ float   g_dis[NN];
__device__ int     g_deg[NN];
__device__ int     g_scan[NN];
__device__ int     g_bsum[256];
__device__ int     g_rowptr[NN + 1];
__device__ int     g_cur[NN];
__device__ int     g_cs[NE];            // CSR src ids (grouped by dst)
__device__ float   g_cw[NE];            // CSR edge weights dis[s]*dis[d]
__device__ __half2 g_t16[NN * 64];      // linear-transform output (fp16)
__device__ __half2 g_h16[NN * 64];      // post-activation features (fp16)
__device__ __half  g_W1h[128 * 128];
__device__ __half  g_Whh[128 * 128];
__device__ __half  g_W2h[128 * 64];

static inline int cdiv(int a, int b) { return (a + b - 1) / b; }

// ---------------------------------------------------------------- weight fp16 pre-convert
__global__ void k_wconv(const float* __restrict__ W1, const float* __restrict__ Wh,
                        const float* __restrict__ W2)
{
    int i = blockIdx.x * blockDim.x + threadIdx.x;   // 0..16383
    g_W1h[i] = __float2half_rn(W1[i]);
    g_Whh[i] = __float2half_rn(Wh[i]);
    if (i < 128 * 64) g_W2h[i] = __float2half_rn(W2[i]);
}

// ---------------------------------------------------------------- degree
__global__ void k_deg_init() {
    int i = blockIdx.x * blockDim.x + threadIdx.x;
    if (i < NN) g_deg[i] = 0;
}

__global__ void k_deg_count(const int* __restrict__ ei) {
    int e = blockIdx.x * blockDim.x + threadIdx.x;
    if (e < NE) atomicAdd(&g_deg[ei[NE + e]], 1);
}

// ---------------------------------------------------------------- scan (2-kernel)
__global__ void k_scan1() {
    __shared__ int s[256];
    int i = blockIdx.x * 256 + threadIdx.x;
    int v = (i < NN) ? g_deg[i] : 0;
    if (i < NN) g_dis[i] = rsqrtf(1.0f + (float)v);
    s[threadIdx.x] = v;
    __syncthreads();
#pragma unroll
    for (int off = 1; off < 256; off <<= 1) {
        int t = (threadIdx.x >= off) ? s[threadIdx.x - off] : 0;
        __syncthreads();
        s[threadIdx.x] += t;
        __syncthreads();
    }
    if (i < NN) g_scan[i] = s[threadIdx.x];          // inclusive
    if (threadIdx.x == 255) g_bsum[blockIdx.x] = s[255];
}

// each block reduces its own prefix of block sums (NB=196 <= 256)
__global__ void k_scan3() {
    __shared__ int s[256];
    int v = (threadIdx.x < blockIdx.x) ? g_bsum[threadIdx.x] : 0;
    s[threadIdx.x] = v;
    __syncthreads();
#pragma unroll
    for (int off = 128; off; off >>= 1) {
        if (threadIdx.x < off) s[threadIdx.x] += s[threadIdx.x + off];
        __syncthreads();
    }
    int boff = s[0];
    int i = blockIdx.x * 256 + threadIdx.x;
    if (i < NN) {
        int rp = g_scan[i] - g_deg[i] + boff;
        g_rowptr[i] = rp;
        g_cur[i] = rp;
    }
    if (i == 0) g_rowptr[NN] = NE;
}

// ---------------------------------------------------------------- CSR scatter
__global__ void k_scatter(const int* __restrict__ ei) {
    int e = blockIdx.x * blockDim.x + threadIdx.x;
    if (e >= NE) return;
    int s = ei[e];
    int d = ei[NE + e];
    int pos = atomicAdd(&g_cur[d], 1);
    g_cs[pos] = s;
    g_cw[pos] = g_dis[s] * g_dis[d];
}

// ---------------------------------------------------------------- fp16 MMA
__device__ __forceinline__ void mma_f16(float* d, const unsigned* a, const unsigned* b) {
    asm("mma.sync.aligned.m16n8k16.row.col.f32.f16.f16.f32 "
        "{%0,%1,%2,%3}, {%4,%5,%6,%7}, {%8,%9}, {%0,%1,%2,%3};"
        : "+f"(d[0]), "+f"(d[1]), "+f"(d[2]), "+f"(d[3])
        : "r"(a[0]), "r"(a[1]), "r"(a[2]), "r"(a[3]), "r"(b[0]), "r"(b[1]));
}

// ---------------------------------------------------------------- fp16 GEMM
// g_t16[M,BN] = fp16( A[M,128] @ B[128,BN] ), fp32 accumulate.
// BM=128, BK=16, 8 warps (4m x 2n), warp tile 32 x BN/2, mma m16n8k16.
// A: fp32 global (layer 1) or g_h16. B: pre-converted fp16 (wsel).
#define ASTH 24   // As row stride (halves)

template <int BN>
__global__ __launch_bounds__(256, 1) void gemm_f16(
    const float* __restrict__ Aparam, int M, int useH, int wsel)
{
    const __half* __restrict__ Bh = (wsel == 0) ? g_W1h : (wsel == 1) ? g_Whh : g_W2h;

    __shared__ __half As[128 * ASTH];   // [m][k]
    __shared__ __half Bt[BN * ASTH];    // [n][k] (transposed)

    const int tid = threadIdx.x;
    const int w = tid >> 5;
    const int lane = tid & 31;
    const int g = lane >> 2;        // 0..7
    const int tig = lane & 3;       // 0..3
    const int warp_m = (w & 3) * 32;
    const int warp_n = (w >> 2) * (BN / 2);
    const int m0 = blockIdx.y * 128;

    constexpr int NT = BN / 16;     // n-tiles per warp
    constexpr int HLD = (16 * BN) / 256;   // B halves per thread (8 or 4)
    __half2* As2 = (__half2*)As;
    __half2* Bt2 = (__half2*)Bt;

    float acc[2][NT][4];
#pragma unroll
    for (int i = 0; i < 2; i++)
#pragma unroll
        for (int j = 0; j < NT; j++)
#pragma unroll
            for (int c = 0; c < 4; c++) acc[i][j][c] = 0.f;

    for (int k0 = 0; k0 < 128; k0 += 16) {
        // ---- load A tile 128x16 halves
        if (useH) {
            int row = tid >> 1;                 // 0..127
            int part = tid & 1;                 // 8 halves each
            uint4 v = make_uint4(0, 0, 0, 0);
            if (m0 + row < M)
                v = *(const uint4*)(g_h16 + (long long)(m0 + row) * 64 + (k0 >> 1) + part * 4);
            *(uint4*)&As[row * ASTH + part * 8] = v;
        } else {
#pragma unroll
            for (int i = 0; i < 2; i++) {
                int idx = tid * 2 + i;          // 0..511
                int row = idx >> 2;             // 0..127
                int kc = (idx & 3) * 4;         // 0,4,8,12
                float4 av = make_float4(0.f, 0.f, 0.f, 0.f);
                if (m0 + row < M)
                    av = *(const float4*)(Aparam + (long long)(m0 + row) * 128 + k0 + kc);
                As2[(row * ASTH + kc) >> 1] = __floats2half2_rn(av.x, av.y);
                As2[(row * ASTH + kc + 2) >> 1] = __floats2half2_rn(av.z, av.w);
            }
        }
        // ---- load B tile 16xBN fp16, store transposed [n][k]
        {
            int krow = tid / (BN / HLD);               // 0..15
            int n0 = (tid % (BN / HLD)) * HLD;
            const __half* src = Bh + (long long)(k0 + krow) * BN + n0;
#pragma unroll
            for (int i = 0; i < HLD; i++)
                Bt[(n0 + i) * ASTH + krow] = src[i];
        }
        __syncthreads();

        // ---- fragments + mma
        unsigned a[2][4];
#pragma unroll
        for (int mt = 0; mt < 2; mt++) {
            int r0 = warp_m + mt * 16 + g;
            a[mt][0] = *(unsigned*)&As2[r0 * (ASTH / 2) + tig];
            a[mt][1] = *(unsigned*)&As2[(r0 + 8) * (ASTH / 2) + tig];
            a[mt][2] = *(unsigned*)&As2[r0 * (ASTH / 2) + tig + 4];
            a[mt][3] = *(unsigned*)&As2[(r0 + 8) * (ASTH / 2) + tig + 4];
        }
#pragma unroll
        for (int nt = 0; nt < NT; nt++) {
            int col = warp_n + nt * 8 + g;
            unsigned b[2];
            b[0] = *(unsigned*)&Bt2[col * (ASTH / 2) + tig];
            b[1] = *(unsigned*)&Bt2[col * (ASTH / 2) + tig + 4];
#pragma unroll
            for (int mt = 0; mt < 2; mt++)
                mma_f16(acc[mt][nt], a[mt], b);
        }
        __syncthreads();
    }

    // epilogue: write fp16 pairs
#pragma unroll
    for (int mt = 0; mt < 2; mt++) {
#pragma unroll
        for (int half = 0; half < 2; half++) {
            int r = m0 + warp_m + mt * 16 + g + half * 8;
            if (r < M) {
#pragma unroll
                for (int nt = 0; nt < NT; nt++) {
                    int c = warp_n + nt * 8 + tig * 2;
                    float2 v = half ? make_float2(acc[mt][nt][2], acc[mt][nt][3])
                                    : make_float2(acc[mt][nt][0], acc[mt][nt][1]);
                    g_t16[(long long)r * (BN / 2) + (c >> 1)] = __floats2half2_rn(v.x, v.y);
                }
            }
        }
    }
}

// ---------------------------------------------------------------- CSR aggregation (F=128)
// 128 threads = 2 nodes/block, 64 threads/node, 2 features/thread.
__global__ __launch_bounds__(128) void k_agg128(const float* __restrict__ bias)
{
    const int node = blockIdx.x * 2 + (threadIdx.x >> 6);
    const int tid  = threadIdx.x & 63;
    if (node >= NN) return;
    const int beg = g_rowptr[node];
    const int end = g_rowptr[node + 1];
    const float ds = g_dis[node];

    float2 self = __half22float2(g_t16[(long long)node * 64 + tid]);
    float ax = ds * ds * self.x;
    float ay = ds * ds * self.y;

    int j = beg;
    for (; j + 4 <= end; j += 4) {
        int   s0 = g_cs[j + 0], s1 = g_cs[j + 1], s2 = g_cs[j + 2], s3 = g_cs[j + 3];
        float w0 = g_cw[j + 0], w1 = g_cw[j + 1], w2 = g_cw[j + 2], w3 = g_cw[j + 3];
        float2 v0 = __half22float2(g_t16[(long long)s0 * 64 + tid]);
        float2 v1 = __half22float2(g_t16[(long long)s1 * 64 + tid]);
        float2 v2 = __half22float2(g_t16[(long long)s2 * 64 + tid]);
        float2 v3 = __half22float2(g_t16[(long long)s3 * 64 + tid]);
        ax += w0 * v0.x + w1 * v1.x + w2 * v2.x + w3 * v3.x;
        ay += w0 * v0.y + w1 * v1.y + w2 * v2.y + w3 * v3.y;
    }
    for (; j < end; j++) {
        float w = g_cw[j];
        float2 v = __half22float2(g_t16[(long long)g_cs[j] * 64 + tid]);
        ax += w * v.x;
        ay += w * v.y;
    }

    float2 bb = *(const float2*)&bias[tid * 2];
    g_h16[(long long)node * 64 + tid] =
        __floats2half2_rn(fmaxf(ax + bb.x, 0.f), fmaxf(ay + bb.y, 0.f));
}

// ---------------------------------------------------------------- fused layer-3 agg + readout (F=64)
// 128 threads = 4 nodes/block, warp per node, 2 features/thread.
__global__ __launch_bounds__(128) void k_final64(
    const float* __restrict__ b2,
    const float* __restrict__ Wout,
    const float* __restrict__ bout,
    float* __restrict__ out)
{
    const int node = blockIdx.x * 4 + (threadIdx.x >> 5);
    const int tid  = threadIdx.x & 31;
    if (node >= NN) return;
    const int beg = g_rowptr[node];
    const int end = g_rowptr[node + 1];
    const float ds = g_dis[node];

    float2 self = __half22float2(g_t16[(long long)node * 32 + tid]);
    float ax = ds * ds * self.x;
    float ay = ds * ds * self.y;

    int j = beg;
    for (; j + 4 <= end; j += 4) {
        int   s0 = g_cs[j + 0], s1 = g_cs[j + 1], s2 = g_cs[j + 2], s3 = g_cs[j + 3];
        float w0 = g_cw[j + 0], w1 = g_cw[j + 1], w2 = g_cw[j + 2], w3 = g_cw[j + 3];
        float2 v0 = __half22float2(g_t16[(long long)s0 * 32 + tid]);
        float2 v1 = __half22float2(g_t16[(long long)s1 * 32 + tid]);
        float2 v2 = __half22float2(g_t16[(long long)s2 * 32 + tid]);
        float2 v3 = __half22float2(g_t16[(long long)s3 * 32 + tid]);
        ax += w0 * v0.x + w1 * v1.x + w2 * v2.x + w3 * v3.x;
        ay += w0 * v0.y + w1 * v1.y + w2 * v2.y + w3 * v3.y;
    }
    for (; j < end; j++) {
        float w = g_cw[j];
        float2 v = __half22float2(g_t16[(long long)g_cs[j] * 32 + tid]);
        ax += w * v.x;
        ay += w * v.y;
    }

    float2 bb = *(const float2*)&b2[tid * 2];
    float vx = ax + bb.x;
    float vy = ay + bb.y;
    *(float2*)&out[NN + (long long)node * 64 + tid * 2] = make_float2(vx, vy);

    float2 ww = *(const float2*)&Wout[tid * 2];
    float p = vx * ww.x + vy * ww.y;
#pragma unroll
    for (int o = 16; o; o >>= 1) p += __shfl_down_sync(0xFFFFFFFFu, p, o);
    if (tid == 0) out[node] = p + bout[0];
}

// ---------------------------------------------------------------- launcher
extern "C" void kernel_launch(void* const* d_in, const int* in_sizes, int n_in,
                              void* d_out, int out_size)
{
    const float* x    = (const float*)d_in[0];
    const int*   ei   = (const int*)d_in[1];     // int32 (JAX x64 disabled)
    const float* W1   = (const float*)d_in[2];
    const float* b1   = (const float*)d_in[3];
    const float* Wh   = (const float*)d_in[4];
    const float* bh   = (const float*)d_in[5];
    const float* W2   = (const float*)d_in[6];
    const float* b2   = (const float*)d_in[7];
    const float* Wout = (const float*)d_in[8];
    const float* bout = (const float*)d_in[9];
    float*       out  = (float*)d_out;

    // Fork: CSR build runs concurrently with weight convert + layer-1 GEMM.
    cudaStream_t s2;
    cudaEvent_t ev_fork, ev_join;
    cudaStreamCreate(&s2);
    cudaEventCreate(&ev_fork);
    cudaEventCreate(&ev_join);

    cudaEventRecord(ev_fork, 0);
    cudaStreamWaitEvent(s2, ev_fork, 0);

    // ---- branch A (s2): normalization + CSR build
    k_deg_init<<<cdiv(NN, 256), 256, 0, s2>>>();
    k_deg_count<<<cdiv(NE, 256), 256, 0, s2>>>(ei);
    k_scan1<<<NB, 256, 0, s2>>>();
    k_scan3<<<NB, 256, 0, s2>>>();
    k_scatter<<<cdiv(NE, 256), 256, 0, s2>>>(ei);
    cudaEventRecord(ev_join, s2);

    // ---- branch B (default stream): weight convert + layer-1 GEMM
    k_wconv<<<64, 256>>>(W1, Wh, W2);
    dim3 gt(1, cdiv(NN, 128));
    gemm_f16<128><<<gt, 256>>>(x, NN, 0, 0);

    // join
    cudaStreamWaitEvent(0, ev_join, 0);

    // layer 1 aggregation
    k_agg128<<<cdiv(NN, 2), 128>>>(b1);
    // layer 2
    gemm_f16<128><<<gt, 256>>>(nullptr, NN, 1, 1);
    k_agg128<<<cdiv(NN, 2), 128>>>(bh);
    // layer 3 (128 -> 64) + fused readout
    gemm_f16<64><<<gt, 256>>>(nullptr, NN, 1, 2);
    k_final64<<<cdiv(NN, 4), 128>>>(b2, Wout, bout, out);
}